// round 5
// baseline (speedup 1.0000x reference)
#include <cuda_runtime.h>
#include <cub/block/block_radix_sort.cuh>
#include <stdint.h>

#define B_   8
#define N_   16384
#define D_   64
#define NTH  1024
#define IPT  16          // NTH*IPT == N_
#define NCMAX 512
#define EPSF 0.1f
#define MINS 5

using SortT = cub::BlockRadixSort<unsigned int, NTH, IPT, unsigned short>;

// scratch (device globals; no runtime allocation). 16B-aligned: accessed as uint4.
__device__ __align__(16) int16_t g_lab[(size_t)B_ * D_ * N_];   // 16 MB (L2-resident)
__device__ int g_ncl[B_ * D_];

// post-sort smem layout (aliases the sort TempStorage region):
//   [0, 32KB)  : halo (NTH*8 floats), later reused as lab16 (N_ int16)
//   [32KB,+128): scf32 (32 floats)    [32KB+128,+128): sci32 (32 ints)
#define HALO_OFF 0
#define LAB_OFF  0
#define SCF_OFF  (NTH * 8 * 4)
#define SCI_OFF  (SCF_OFF + 32 * 4)
#define POST_BYTES (SCI_OFF + 32 * 4)

// EXT(j): sorted value at local position j in [-4, 19] relative to this thread's
// 16-element chunk. j is a compile-time constant after unroll -> register select.
#define EXT(j) ((j) < 0 ? Lh[(j) + 4] : ((j) < 16 ? x[(j)] : Rh[(j) - 16]))

__global__ void __launch_bounds__(NTH, 1) k_dbscan(const float* __restrict__ feat) {
    extern __shared__ __align__(16) unsigned char smem[];
    const int bd = blockIdx.x;
    const int b = bd >> 6, d = bd & 63;
    const float* base = feat + ((size_t)b * N_ * D_) + d;
    const int t = threadIdx.x;
    const int lane = t & 31, wid = t >> 5;
    const unsigned FULL = 0xFFFFFFFFu;

    unsigned int keys[IPT];
    unsigned short vals[IPT];
#pragma unroll
    for (int k = 0; k < IPT; k++) {
        int n = t + k * NTH;                       // striped gather (stride D_)
        unsigned u = __float_as_uint(__ldg(base + (size_t)n * D_));
        u ^= (u & 0x80000000u) ? 0xFFFFFFFFu : 0x80000000u;   // order-preserving
        keys[k] = u;
        vals[k] = (unsigned short)n;
    }

    SortT(*reinterpret_cast<SortT::TempStorage*>(smem)).Sort(keys, vals); // blocked
    __syncthreads();

    // sorted values -> registers
    float x[IPT];
#pragma unroll
    for (int k = 0; k < IPT; k++) {
        unsigned u = keys[k];
        u ^= (u & 0x80000000u) ? 0x80000000u : 0xFFFFFFFFu;
        x[k] = __uint_as_float(u);
    }

    float* halo = (float*)(smem + HALO_OFF);
    unsigned short* lab16 = (unsigned short*)(smem + LAB_OFF);
    float* scf32 = (float*)(smem + SCF_OFF);
    int*   sci32 = (int*)(smem + SCI_OFF);

    // halo exchange: publish first 4 and last 4 sorted values of each chunk
    halo[t * 8 + 0] = x[0];  halo[t * 8 + 1] = x[1];
    halo[t * 8 + 2] = x[2];  halo[t * 8 + 3] = x[3];
    halo[t * 8 + 4] = x[12]; halo[t * 8 + 5] = x[13];
    halo[t * 8 + 6] = x[14]; halo[t * 8 + 7] = x[15];
    __syncthreads();
    float Lh[4], Rh[4];
#pragma unroll
    for (int j = 0; j < 4; j++) {
        Lh[j] = (t > 0)       ? halo[(t - 1) * 8 + 4 + j] : 0.0f;  // masked by validity
        Rh[j] = (t < NTH - 1) ? halo[(t + 1) * 8 + j]     : 0.0f;
    }

    // ---- core test: 5-window check (exact equiv of the two searchsorteds) ----
    const int gbase = t * IPT;
    unsigned coreb = 0;
#pragma unroll
    for (int k = 0; k < IPT; k++) {
        float xv = x[k];
        float loth = xv - EPSF, hith = xv + EPSF;
        bool c = false;
#pragma unroll
        for (int o = 0; o < MINS; o++) {
            int jl = k - o, jr = k - o + 4;
            bool valid = (gbase + jl >= 0) && (gbase + jr < N_);
            c = c || (valid && (EXT(jl) >= loth) && (EXT(jr) <= hith));
        }
        coreb |= ((unsigned)c) << k;
    }

    const float INF = __int_as_float(0x7f800000);

    // ---- suffix-min of core values (shuffle scan): rvl[k] = nearest core val right ----
    float rvl[IPT];
    {
        float agg = INF;
#pragma unroll
        for (int k = 0; k < IPT; k++)
            agg = fminf(agg, ((coreb >> k) & 1) ? x[k] : INF);
        float inc = agg;
#pragma unroll
        for (int off = 1; off < 32; off <<= 1) {
            float w = __shfl_down_sync(FULL, inc, off);
            if (lane + off < 32) inc = fminf(inc, w);
        }
        if (lane == 0) scf32[wid] = inc;            // whole-warp min
        __syncthreads();
        float warp_tail = INF;
        for (int j = wid + 1; j < 32; j++) warp_tail = fminf(warp_tail, scf32[j]);
        float excl_w = __shfl_down_sync(FULL, inc, 1);
        if (lane == 31) excl_w = INF;
        float run = fminf(excl_w, warp_tail);       // suffix over later threads
#pragma unroll
        for (int k = IPT - 1; k >= 0; k--) {
            if ((coreb >> k) & 1) run = x[k];       // ascending -> min is self
            rvl[k] = run;
        }
        __syncthreads();                            // protect scf32 before reuse
    }

    // ---- forward aggregates per chunk ----
    float firstc = INF, prev = -INF;
    int cint = 0;
    bool hasc = false;
#pragma unroll
    for (int k = 0; k < IPT; k++) {
        if ((coreb >> k) & 1) {
            float xv = x[k];
            if (!hasc) { firstc = xv; hasc = true; }
            else        cint += (xv - prev > EPSF);
            prev = xv;
        }
    }
    // prefix-max of last-core-value (shuffle scan) -> lvin
    float incp = prev;
#pragma unroll
    for (int off = 1; off < 32; off <<= 1) {
        float w = __shfl_up_sync(FULL, incp, off);
        if (lane >= off) incp = fmaxf(incp, w);
    }
    if (lane == 31) scf32[wid] = incp;
    __syncthreads();
    float warp_head = -INF;
    for (int j = 0; j < wid; j++) warp_head = fmaxf(warp_head, scf32[j]);
    float exclp = __shfl_up_sync(FULL, incp, 1);
    if (lane == 0) exclp = -INF;
    float lvin = fmaxf(exclp, warp_head);           // last core value before chunk

    // prefix-sum of new-cluster counts -> cidin
    int tc = cint + (int)(hasc && (firstc - lvin > EPSF));
    int incs = tc;
#pragma unroll
    for (int off = 1; off < 32; off <<= 1) {
        int w = __shfl_up_sync(FULL, incs, off);
        if (lane >= off) incs += w;
    }
    if (lane == 31) sci32[wid] = incs;
    __syncthreads();
    int head = 0;
    for (int j = 0; j < wid; j++) head += sci32[j];
    int excls = __shfl_up_sync(FULL, incs, 1);
    if (lane == 0) excls = 0;
    int cidin = head + excls;

    // ---- labeling; scatter into smem in ORIGINAL node order (cheap smem scatter) ----
    float lv = lvin;
    int cid = cidin - 1;
#pragma unroll
    for (int k = 0; k < IPT; k++) {
        float xv = x[k];
        int lab;
        if ((coreb >> k) & 1) {
            cid += (xv - lv > EPSF);
            lv = xv;
            lab = cid;
        } else {
            float dl = xv - lv;          // +inf if no core on the left
            float dr = rvl[k] - xv;      // +inf if no core on the right
            if (fminf(dl, dr) <= EPSF)
                lab = (dl <= dr) ? cid : (cid + ((rvl[k] - lv > EPSF) ? 1 : 0));
            else
                lab = -1;
        }
        lab16[vals[k]] = (unsigned short)(short)lab;
    }
    if (t == NTH - 1) g_ncl[bd] = cid + 1;
    __syncthreads();

    // ---- coalesced streaming store of the 32 KB label array (default policy:
    //      we WANT g_lab L2-resident for k_rows) ----
    {
        const uint4* src = (const uint4*)lab16;
        uint4* dst = (uint4*)(g_lab + (size_t)bd * N_);
        dst[t]       = src[t];
        dst[t + NTH] = src[t + NTH];
    }
}

// 64 points per block; assemble each 512-float row in smem, stream out coalesced.
__global__ void __launch_bounds__(256) k_rows(float* __restrict__ out) {
    __shared__ int   ncl_s[D_];
    __shared__ int   off_s[D_];
    __shared__ short lab_s[64 * 66];        // [p][d], pad 66 to avoid bank conflicts
    __shared__ float rows[8][NCMAX];

    const int blk = blockIdx.x;
    const int b = blk >> 8;                 // 256 blocks per batch (16384/64 points)
    const int n0 = (blk & 255) << 6;
    const int tid = threadIdx.x;

    if (tid < D_) ncl_s[tid] = g_ncl[b * D_ + tid];
    __syncthreads();
    if (tid < D_) {                          // exclusive prefix over dims
        int s = 0;
        for (int j = 0; j < tid; j++) s += ncl_s[j];
        off_s[tid] = s;
    }
#pragma unroll
    for (int j = 0; j < 16; j++) {           // stage 64x64 labels, coalesced (L2 hits)
        int idx = j * 256 + tid;
        int dd = idx >> 6, p = idx & 63;
        lab_s[p * 66 + dd] = g_lab[((size_t)(b * D_ + dd)) * N_ + n0 + p];
    }
    __syncthreads();

    const int w = tid >> 5, l = tid & 31;
    const float4 z = make_float4(0.f, 0.f, 0.f, 0.f);
    float4* r4 = (float4*)rows[w];
#pragma unroll
    for (int pi = 0; pi < 8; pi++) {
        int p = (w << 3) + pi;
        r4[l] = z; r4[l + 32] = z; r4[l + 64] = z; r4[l + 96] = z;
        __syncwarp();
        int c0 = lab_s[p * 66 + 2 * l];
        int c1 = lab_s[p * 66 + 2 * l + 1];
        if (c0 >= 0) { int g = c0 + off_s[2 * l];     if (g < NCMAX) rows[w][g] = 1.0f; }
        if (c1 >= 0) { int g = c1 + off_s[2 * l + 1]; if (g < NCMAX) rows[w][g] = 1.0f; }
        __syncwarp();
        // streaming (evict-first) stores: keep the 256 MB output out of L2 so
        // g_lab stays resident for all later blocks
        float4* o4 = (float4*)(out + ((size_t)b * N_ + n0 + p) * NCMAX);
        __stcs(o4 + l,      r4[l]);
        __stcs(o4 + l + 32, r4[l + 32]);
        __stcs(o4 + l + 64, r4[l + 64]);
        __stcs(o4 + l + 96, r4[l + 96]);
        __syncwarp();
    }
}

extern "C" void kernel_launch(void* const* d_in, const int* in_sizes, int n_in,
                              void* d_out, int out_size) {
    const float* feat = (const float*)d_in[0];
    float* out = (float*)d_out;

    size_t smem1 = sizeof(SortT::TempStorage);
    if (smem1 < (size_t)POST_BYTES) smem1 = POST_BYTES;
    cudaFuncSetAttribute(k_dbscan, cudaFuncAttributeMaxDynamicSharedMemorySize, (int)smem1);

    k_dbscan<<<B_ * D_, NTH, smem1>>>(feat);
    k_rows<<<(B_ * N_) / 64, 256>>>(out);
}

// round 14
// speedup vs baseline: 1.5252x; 1.5252x over previous
#include <cuda_runtime.h>
#include <stdint.h>

#define B_    8
#define N_    16384
#define D_    64
#define NCMAX 512
#define EPSF  0.1f
#define MINS  5
#define NB    4096        // value buckets
#define CMAX  8192        // max clusters per (b,d)  (provable bound 2N/5+1)

// 16B-aligned: g_featT is read with float4 (LDG.128)
__device__ __align__(16) float g_featT[(size_t)B_ * D_ * N_];   // 16 MB transposed input
__device__ __align__(16) float g_F[(size_t)B_ * D_ * CMAX];     // first core value per cluster
__device__ __align__(16) float g_L[(size_t)B_ * D_ * CMAX];     // last  core value per cluster
__device__ int g_ncl[B_ * D_];

#define INFF __int_as_float(0x7f800000)

// bank-conflict-free padded layout for the sorted array:
// logical index i -> physical index i + i/32  (lane stride 33 -> distinct banks)
// NOTE: macro double-evaluates its argument — pass ONLY pure expressions.
#define P(i) ((i) + ((i) >> 5))
#define XS_PHYS (N_ + N_ / 32)        // 16896 floats

// ------------------------------------------------------------------ transpose
__global__ void __launch_bounds__(256) k_tr(const float* __restrict__ in) {
    __shared__ float tile[32][33];
    const int n0 = blockIdx.x * 32, d0 = blockIdx.y * 32, b = blockIdx.z;
    const int tx = threadIdx.x, ty = threadIdx.y;          // (32, 8)
    const float* src = in + ((size_t)b * N_ + n0) * D_ + d0;
#pragma unroll
    for (int i = 0; i < 4; i++)
        tile[ty + 8 * i][tx] = src[(size_t)(ty + 8 * i) * D_ + tx];
    __syncthreads();
    float* dst = g_featT + ((size_t)b * D_ + d0) * N_ + n0;
#pragma unroll
    for (int i = 0; i < 4; i++)
        dst[(size_t)(ty + 8 * i) * N_ + tx] = tile[tx][ty + 8 * i];
}

// ------------------------------------------------------- bucket sort + dbscan
// dynamic smem: xs[XS_PHYS] | cnt[NB] | stgF[32] | stgI[16]
#define SM_XS  0
#define SM_CNT (XS_PHYS * 4)
#define SM_STG (SM_CNT + NB * 4)
#define SMEM1_BYTES (SM_STG + 32 * 4 + 16 * 4)

__device__ __forceinline__ int bkt_of(float x) {
    int b = __float2int_rd((x + 8.0f) * 256.0f);           // monotone in x
    return min(max(b, 0), NB - 1);
}

__global__ void __launch_bounds__(512, 2) k_dbscan() {
    extern __shared__ __align__(16) unsigned char smem[];
    float* xs   = (float*)(smem + SM_XS);
    int*   cnt  = (int*)(smem + SM_CNT);
    float* stgF = (float*)(smem + SM_STG);                 // [0,16) max-scan, [16,32) min-scan
    int*   stgI = (int*)(smem + SM_STG + 128);

    const int bd = blockIdx.x;
    const int t = threadIdx.x, lane = t & 31, w = t >> 5;  // 16 warps
    const unsigned FULL = 0xFFFFFFFFu;
    const float4* col4 = (const float4*)(g_featT + (size_t)bd * N_);

    // 1. zero histogram
    for (int i = t; i < NB; i += 512) cnt[i] = 0;
    __syncthreads();
    // 2. histogram
    for (int i = t; i < N_ / 4; i += 512) {
        float4 v = col4[i];
        atomicAdd(&cnt[bkt_of(v.x)], 1);
        atomicAdd(&cnt[bkt_of(v.y)], 1);
        atomicAdd(&cnt[bkt_of(v.z)], 1);
        atomicAdd(&cnt[bkt_of(v.w)], 1);
    }
    __syncthreads();
    // 3. exclusive prefix over 4096 counters (8 per thread)
    {
        int c8[8], s = 0;
#pragma unroll
        for (int j = 0; j < 8; j++) { c8[j] = cnt[t * 8 + j]; s += c8[j]; }
        int inc = s;
#pragma unroll
        for (int off = 1; off < 32; off <<= 1) {
            int v = __shfl_up_sync(FULL, inc, off);
            if (lane >= off) inc += v;
        }
        if (lane == 31) stgI[w] = inc;
        __syncthreads();
        int base = 0;
        for (int j = 0; j < w; j++) base += stgI[j];
        int run = base + inc - s;                           // exclusive start
#pragma unroll
        for (int j = 0; j < 8; j++) { cnt[t * 8 + j] = run; run += c8[j]; }
        __syncthreads();
    }
    // 4. scatter values into bucket-contiguous (logical) order, padded physical.
    //    Atomics hoisted into temps: P() double-evaluates its argument!
    for (int i = t; i < N_ / 4; i += 512) {
        float4 v = col4[i];
        int p0 = atomicAdd(&cnt[bkt_of(v.x)], 1);
        int p1 = atomicAdd(&cnt[bkt_of(v.y)], 1);
        int p2 = atomicAdd(&cnt[bkt_of(v.z)], 1);
        int p3 = atomicAdd(&cnt[bkt_of(v.w)], 1);
        xs[P(p0)] = v.x;
        xs[P(p1)] = v.y;
        xs[P(p2)] = v.z;
        xs[P(p3)] = v.w;
    }
    __syncthreads();                                        // cnt[i] now = end of bucket i
    // 5. insertion sort within each bucket (one thread per bucket)
    for (int i = t; i < NB; i += 512) {
        int st = i ? cnt[i - 1] : 0, en = cnt[i];
        for (int a = st + 1; a < en; a++) {
            float key = xs[P(a)];
            int b2 = a - 1;
            while (b2 >= st && xs[P(b2)] > key) { xs[P(b2 + 1)] = xs[P(b2)]; b2--; }
            xs[P(b2 + 1)] = key;
        }
    }
    __syncthreads();

    // 6. core flags via 5-window test (exact equiv of the two searchsorteds)
    const int base0 = t * 32;
    unsigned coreb = 0;
#pragma unroll
    for (int g = 0; g < 4; g++) {
        float a[16];
        const int pg = base0 + g * 8;                       // positions pg..pg+7
#pragma unroll
        for (int j = 0; j < 16; j++) {
            int idx = pg - 4 + j;
            int idxc = min(max(idx, 0), N_ - 1);            // clamp: never OOB smem read
            a[j] = xs[P(idxc)];                             // garbage masked by 'valid'
        }
#pragma unroll
        for (int k = 0; k < 8; k++) {
            float xv = a[k + 4];
            float lo = xv - EPSF, hi = xv + EPSF;
            bool c = false;
#pragma unroll
            for (int o = 0; o < MINS; o++) {
                int il = pg + k - o, ir = il + 4;
                bool valid = (il >= 0) && (ir < N_);
                c = c || (valid && (a[k - o + 4] >= lo) && (a[k - o + 8] <= hi));
            }
            coreb |= ((unsigned)c) << (g * 8 + k);
        }
    }

    // 7. per-chunk forward aggregates
    float firstc = INFF, lastc = -INFF;
    int cint = 0;
    bool hasc = false;
#pragma unroll
    for (int k = 0; k < 32; k++) {
        if ((coreb >> k) & 1) {
            float xv = xs[P(base0 + k)];
            if (!hasc) { firstc = xv; hasc = true; }
            else        cint += (xv - lastc > EPSF);
            lastc = xv;
        }
    }

    // 8. scans over 512 threads: prefix-max(lastc) -> lvin, suffix-min(firstc) -> rvin
    float incp = lastc;
#pragma unroll
    for (int off = 1; off < 32; off <<= 1) {
        float v = __shfl_up_sync(FULL, incp, off);
        if (lane >= off) incp = fmaxf(incp, v);
    }
    float incm = firstc;
#pragma unroll
    for (int off = 1; off < 32; off <<= 1) {
        float v = __shfl_down_sync(FULL, incm, off);
        if (lane + off < 32) incm = fminf(incm, v);
    }
    if (lane == 31) stgF[w] = incp;
    if (lane == 0)  stgF[16 + w] = incm;
    __syncthreads();
    float basemax = -INFF;
    for (int j = 0; j < w; j++) basemax = fmaxf(basemax, stgF[j]);
    float exclp = __shfl_up_sync(FULL, incp, 1);
    if (lane == 0) exclp = -INFF;
    float lvin = fmaxf(basemax, exclp);                     // last core value before chunk

    float tailmin = INFF;
    for (int j = w + 1; j < 16; j++) tailmin = fminf(tailmin, stgF[16 + j]);
    float exclm = __shfl_down_sync(FULL, incm, 1);
    if (lane == 31) exclm = INFF;
    float rvin = fminf(tailmin, exclm);                     // first core value after chunk

    // prefix-sum of new-cluster counts -> cidin
    int tc = cint + (int)(hasc && (firstc - lvin > EPSF));
    int incs = tc;
#pragma unroll
    for (int off = 1; off < 32; off <<= 1) {
        int v = __shfl_up_sync(FULL, incs, off);
        if (lane >= off) incs += v;
    }
    if (lane == 31) stgI[w] = incs;
    __syncthreads();
    int head = 0;
    for (int j = 0; j < w; j++) head += stgI[j];
    int excls = __shfl_up_sync(FULL, incs, 1);
    if (lane == 0) excls = 0;
    int cidin = head + excls;

    // 9. backward: "last core of its cluster" flags
    unsigned lastm = 0;
    {
        float run = rvin;
#pragma unroll
        for (int k = 31; k >= 0; k--) {
            if ((coreb >> k) & 1) {
                float xv = xs[P(base0 + k)];
                if (run - xv > EPSF) lastm |= 1u << k;      // run = +inf -> true
                run = xv;
            }
        }
    }

    // 10. forward: write F (on start) and L (on last) per cluster
    {
        float* Fp = g_F + (size_t)bd * CMAX;
        float* Lp = g_L + (size_t)bd * CMAX;
        float lv = lvin;
        int cid = cidin - 1;
#pragma unroll
        for (int k = 0; k < 32; k++) {
            if ((coreb >> k) & 1) {
                float xv = xs[P(base0 + k)];
                if (xv - lv > EPSF) { cid++; Fp[cid] = xv; }
                if ((lastm >> k) & 1) Lp[cid] = xv;
                lv = xv;
            }
        }
        if (t == 511) g_ncl[bd] = cid + 1;
    }
}

// --------------------------------------- fused labeling + incidence row build
__global__ void __launch_bounds__(256) k_out(const float* __restrict__ feat,
                                             float* __restrict__ out) {
    __shared__ int   ncl_s[D_];
    __shared__ int   off_s[D_];
    __shared__ int   sdx[D_ + 1];
    __shared__ float Fs[640];
    __shared__ float Ls[640];
    __shared__ __align__(16) float rows[8][NCMAX];   // float4-accessed

    const int blk = blockIdx.x;
    const int b = blk >> 8;                  // 256 blocks per batch (64 points each)
    const int n0 = (blk & 255) << 6;
    const int tid = threadIdx.x;

    if (tid < D_) ncl_s[tid] = g_ncl[b * D_ + tid];
    __syncthreads();
    if (tid == 0) {                           // tiny serial prefix over 64 dims
        int off = 0; sdx[0] = 0;
        for (int d = 0; d < D_; d++) {
            off_s[d] = off;
            int cap = NCMAX - off;            // clusters with glb < NCMAX matter
            int st = ncl_s[d];
            int lim = (cap > 0 ? cap : 0) + 1;
            if (st > lim) st = lim;
            sdx[d + 1] = sdx[d] + st;
            off += ncl_s[d];
        }
    }
    __syncthreads();
    const int T = sdx[D_];
    for (int e = tid; e < T; e += 256) {      // gather compacted F/L into smem
        int lo2 = 0, hi2 = D_;                // first d with sdx[d+1] > e
        while (lo2 < hi2) { int m = (lo2 + hi2) >> 1; if (sdx[m + 1] <= e) lo2 = m + 1; else hi2 = m; }
        int d = lo2, c = e - sdx[d];
        Fs[e] = g_F[((size_t)(b * D_ + d)) * CMAX + c];
        Ls[e] = g_L[((size_t)(b * D_ + d)) * CMAX + c];
    }
    __syncthreads();

    const int w = tid >> 5, l = tid & 31;
    const float4 z = make_float4(0.f, 0.f, 0.f, 0.f);
    float4* r4 = (float4*)rows[w];
#pragma unroll 1
    for (int pi = 0; pi < 8; pi++) {
        const int n = n0 + w * 8 + pi;
        r4[l] = z; r4[l + 32] = z; r4[l + 64] = z; r4[l + 96] = z;
        __syncwarp();
        const float2 xv2 = ((const float2*)(feat + ((size_t)(b * N_ + n)) * D_))[l];
#pragma unroll
        for (int q = 0; q < 2; q++) {
            const int d = l * 2 + q;
            const float x = q ? xv2.y : xv2.x;
            const int s0 = sdx[d], s1 = sdx[d + 1];
            int lo3 = s0, hi3 = s1;           // largest j with Fs[j] <= x
            while (lo3 < hi3) { int m = (lo3 + hi3) >> 1; if (Fs[m] <= x) lo3 = m + 1; else hi3 = m; }
            const int j = lo3 - 1;
            int lab;
            if (j >= s0 && x <= Ls[j]) lab = j - s0;         // inside core span
            else {
                float dl = (j >= s0) ? (x - Ls[j]) : INFF;   // nearest core left
                float dr = (lo3 < s1) ? (Fs[lo3] - x) : INFF; // nearest core right
                if (fminf(dl, dr) <= EPSF) lab = (dl <= dr) ? (j - s0) : (lo3 - s0);
                else lab = -1;
            }
            if (lab >= 0) {
                int g = lab + off_s[d];
                if ((unsigned)g < NCMAX) rows[w][g] = 1.0f;
            }
        }
        __syncwarp();
        float4* o4 = (float4*)(out + ((size_t)(b * N_ + n)) * NCMAX);
        __stcs(o4 + l,      r4[l]);
        __stcs(o4 + l + 32, r4[l + 32]);
        __stcs(o4 + l + 64, r4[l + 64]);
        __stcs(o4 + l + 96, r4[l + 96]);
        __syncwarp();
    }
}

extern "C" void kernel_launch(void* const* d_in, const int* in_sizes, int n_in,
                              void* d_out, int out_size) {
    const float* feat = (const float*)d_in[0];
    float* out = (float*)d_out;

    cudaFuncSetAttribute(k_dbscan, cudaFuncAttributeMaxDynamicSharedMemorySize, SMEM1_BYTES);

    dim3 gtr(N_ / 32, D_ / 32, B_);
    k_tr<<<gtr, dim3(32, 8)>>>(feat);
    k_dbscan<<<B_ * D_, 512, SMEM1_BYTES>>>();
    k_out<<<(B_ * N_) / 64, 256>>>(feat, out);
}